// round 10
// baseline (speedup 1.0000x reference)
#include <cuda_runtime.h>
#include <cstdint>

// ---------------------------------------------------------------------------
// Problem constants
// ---------------------------------------------------------------------------
#define N_WORD   30000
#define N_TOPIC  1000
#define N_DOC    15000
#define D_IN     300
#define D_OUT    128

#define E_WW 800000
#define E_WT 400000
#define E_WD 600000
#define E_TD 300000
#define E_TT 150000
#define E_TOT (E_WW + E_WT + E_WD + E_TD + E_TT)   // 2,250,000
// etype ids: 0=ww, 1=wt, 2=wd, 3=td, 4=tt

#define N_WD (N_WORD + N_DOC)                      // 45,000 warp-per-node nodes

// GEMM tile bookkeeping: 128-row tiles per etype
#define T_W  235   // ceil(30000/128)
#define T_T  8     // ceil(1000/128)
#define TILES_TOTAL (3 * T_W + 2 * T_T)            // 721
#define KCH  32
#define NCH  10    // ceil(300/32) -> padded K=320

// ---------------------------------------------------------------------------
// Static device scratch (no allocation allowed)
// ---------------------------------------------------------------------------
__device__ float g_Wh_ww[(size_t)N_WORD  * D_OUT];
__device__ float g_Wh_wt[(size_t)N_WORD  * D_OUT];
__device__ float g_Wh_wd[(size_t)N_WORD  * D_OUT];
__device__ float g_Wh_td[(size_t)N_TOPIC * D_OUT];
__device__ float g_Wh_tt[(size_t)N_TOPIC * D_OUT];

__device__ int g_deg_ww[N_WORD];  __device__ int g_off_ww[N_WORD + 1];
__device__ int g_deg_wt[N_TOPIC]; __device__ int g_off_wt[N_TOPIC + 1];
__device__ int g_deg_wd[N_DOC];   __device__ int g_off_wd[N_DOC + 1];
__device__ int g_deg_td[N_DOC];   __device__ int g_off_td[N_DOC + 1];
__device__ int g_deg_tt[N_TOPIC]; __device__ int g_off_tt[N_TOPIC + 1];

// per-edge rank within its dst bucket (flat over all etypes)
__device__ int g_rank[E_TOT];

// dst-sorted packed (src, w) pairs
__device__ uint2 g_pair_ww[E_WW];
__device__ uint2 g_pair_wt[E_WT];
__device__ uint2 g_pair_wd[E_WD];
__device__ uint2 g_pair_td[E_TD];
__device__ uint2 g_pair_tt[E_TT];

__device__ __forceinline__ float* Wh_ptr(int et) {
    switch (et) { case 0: return g_Wh_ww; case 1: return g_Wh_wt; case 2: return g_Wh_wd;
                  case 3: return g_Wh_td; default: return g_Wh_tt; }
}
__device__ __forceinline__ int* deg_ptr(int et) {
    switch (et) { case 0: return g_deg_ww; case 1: return g_deg_wt; case 2: return g_deg_wd;
                  case 3: return g_deg_td; default: return g_deg_tt; }
}
__device__ __forceinline__ int* off_ptr(int et) {
    switch (et) { case 0: return g_off_ww; case 1: return g_off_wt; case 2: return g_off_wd;
                  case 3: return g_off_td; default: return g_off_tt; }
}
__device__ __forceinline__ uint2* pair_ptr(int et) {
    switch (et) { case 0: return g_pair_ww; case 1: return g_pair_wt; case 2: return g_pair_wd;
                  case 3: return g_pair_td; default: return g_pair_tt; }
}
__device__ __forceinline__ int ndst_of(int et) {
    switch (et) { case 0: return N_WORD; case 1: return N_TOPIC; case 2: return N_DOC;
                  case 3: return N_DOC; default: return N_TOPIC; }
}

// ---------------------------------------------------------------------------
// Pointer bundles
// ---------------------------------------------------------------------------
struct EdgeArgs {
    const int*   src[5];
    const int*   dst[5];
    const float* w[5];
};
struct GemmArgs {
    const float* featW;
    const float* featT;
    const float* Wm[5];
    const float* bias[5];
};

// flat-edge -> (etype, local index)
__device__ __forceinline__ void edge_map(int i, int& et, int& j) {
    if (i < E_WW)                        { et = 0; j = i; }
    else if (i < E_WW + E_WT)            { et = 1; j = i - E_WW; }
    else if (i < E_WW + E_WT + E_WD)     { et = 2; j = i - (E_WW + E_WT); }
    else if (i < E_TOT - E_TT)           { et = 3; j = i - (E_WW + E_WT + E_WD); }
    else                                 { et = 4; j = i - (E_TOT - E_TT); }
}

// ---------------------------------------------------------------------------
// Kernel 1: zero degree arrays (blockIdx.y = etype)
// ---------------------------------------------------------------------------
__global__ void zero_deg_kernel() {
    int et = blockIdx.y;
    int n = ndst_of(et);
    int i = blockIdx.x * blockDim.x + threadIdx.x;
    if (i < n) deg_ptr(et)[i] = 0;
}

// ---------------------------------------------------------------------------
// Kernel 2: fused histogram; atomicAdd return value = per-edge rank
// ---------------------------------------------------------------------------
__global__ void hist_all_kernel(EdgeArgs ea) {
    int i = blockIdx.x * blockDim.x + threadIdx.x;
    if (i >= E_TOT) return;
    int et, j; edge_map(i, et, j);
    g_rank[i] = atomicAdd(&deg_ptr(et)[ea.dst[et][j]], 1);
}

// ---------------------------------------------------------------------------
// Kernel 3: fused scan, one block per etype
// ---------------------------------------------------------------------------
__global__ void scan_all_kernel() {
    const int et = blockIdx.x;
    const int n = ndst_of(et);
    int* deg = deg_ptr(et);
    int* off = off_ptr(et);
    __shared__ int partial[1024];
    int t = threadIdx.x;
    int chunk = (n + 1023) >> 10;
    int beg = t * chunk;
    int end = min(beg + chunk, n);
    int s = 0;
    for (int i = beg; i < end; i++) s += deg[i];
    partial[t] = s;
    __syncthreads();
    for (int d = 1; d < 1024; d <<= 1) {
        int v = (t >= d) ? partial[t - d] : 0;
        __syncthreads();
        partial[t] += v;
        __syncthreads();
    }
    int run = (t == 0) ? 0 : partial[t - 1];
    for (int i = beg; i < end; i++) {
        off[i] = run;
        run += deg[i];
    }
    if (t == 1023) off[n] = partial[1023];
}

// ---------------------------------------------------------------------------
// Kernel 4: atomic-free fill of dst-sorted packed (src, w) pairs
// ---------------------------------------------------------------------------
__global__ void fill_all_kernel(EdgeArgs ea) {
    int i = blockIdx.x * blockDim.x + threadIdx.x;
    if (i >= E_TOT) return;
    int et, j; edge_map(i, et, j);
    int d    = ea.dst[et][j];
    int slot = off_ptr(et)[d] + g_rank[i];
    uint2 p;
    p.x = (unsigned)ea.src[et][j];
    p.y = __float_as_uint(ea.w[et][j]);
    pair_ptr(et)[slot] = p;
}

// ---------------------------------------------------------------------------
// Kernel 5: fused tf32 GEMM with cp.async double buffering.
// Raw fp32 tiles staged in smem; tf32 cvt at frag-load time.
// ---------------------------------------------------------------------------
__device__ __forceinline__ unsigned f2tf32(float x) {
    unsigned u; asm("cvt.rna.tf32.f32 %0, %1;" : "=r"(u) : "f"(x)); return u;
}
__device__ __forceinline__ void mma_tf32(float* c, const unsigned* a, const unsigned* b) {
    asm volatile(
        "mma.sync.aligned.m16n8k8.row.col.f32.tf32.tf32.f32 "
        "{%0,%1,%2,%3}, {%4,%5,%6,%7}, {%8,%9}, {%0,%1,%2,%3};\n"
        : "+f"(c[0]), "+f"(c[1]), "+f"(c[2]), "+f"(c[3])
        : "r"(a[0]), "r"(a[1]), "r"(a[2]), "r"(a[3]), "r"(b[0]), "r"(b[1]));
}
__device__ __forceinline__ void cp_async16(void* smem, const void* gmem, int valid_bytes) {
    unsigned sa = (unsigned)__cvta_generic_to_shared(smem);
    asm volatile("cp.async.cg.shared.global [%0], [%1], 16, %2;\n"
                 :: "r"(sa), "l"(gmem), "r"(valid_bytes));
}

__global__ void __launch_bounds__(256, 2)
gemm_tf32_kernel(GemmArgs ga) {
    __shared__ float Af[2][128][36];    // [buf][row][k]  (stride 36: conflict-free frags)
    __shared__ float Bf[2][32][136];    // [buf][k][n]    (stride 136: conflict-free frags)

    int bt = blockIdx.x;
    int et, tile;
    if      (bt < T_W)                 { et = 0; tile = bt; }
    else if (bt < 2 * T_W)             { et = 1; tile = bt - T_W; }
    else if (bt < 3 * T_W)             { et = 2; tile = bt - 2 * T_W; }
    else if (bt < 3 * T_W + T_T)       { et = 3; tile = bt - 3 * T_W; }
    else                               { et = 4; tile = bt - (3 * T_W + T_T); }

    const float* A    = (et < 3) ? ga.featW : ga.featT;
    const int    M    = (et < 3) ? N_WORD : N_TOPIC;
    const float* Wm   = ga.Wm[et];
    const float* bias = ga.bias[et];
    float*       C    = Wh_ptr(et);

    const int row0 = tile * 128;
    const int tid  = threadIdx.x;
    const int lane = tid & 31, wid = tid >> 5;
    const int wm = wid & 3, wn = wid >> 2;       // warp grid 4 x 2
    const int g  = lane >> 2, tg = lane & 3;     // groupID / thread-in-group

    float acc[2][8][4];
#pragma unroll
    for (int mi = 0; mi < 2; mi++)
#pragma unroll
        for (int ni = 0; ni < 8; ni++)
#pragma unroll
            for (int q = 0; q < 4; q++) acc[mi][ni][q] = 0.0f;

    // ---- async tile loader (raw fp32, zero-fill out-of-range)
    auto load_chunk = [&](int k0, int buf) {
#pragma unroll
        for (int it = 0; it < 4; it++) {
            int slot = it * 256 + tid;           // 0..1023
            int r = slot >> 3, kq = slot & 7;
            int gr = row0 + r, gk = k0 + kq * 4;
            int ok = (gr < M && gk + 4 <= D_IN);
            const float* gp = A + (size_t)(ok ? gr : 0) * D_IN + (ok ? gk : 0);
            cp_async16(&Af[buf][r][kq * 4], gp, ok ? 16 : 0);
        }
#pragma unroll
        for (int it = 0; it < 4; it++) {
            int slot = it * 256 + tid;           // 0..1023
            int kk = slot >> 5, cq = slot & 31;
            int gk = k0 + kk;
            int ok = (gk < D_IN);
            const float* gp = Wm + (size_t)(ok ? gk : 0) * D_OUT + cq * 4;
            cp_async16(&Bf[buf][kk][cq * 4], gp, ok ? 16 : 0);
        }
        asm volatile("cp.async.commit_group;\n");
    };

    load_chunk(0, 0);
    for (int c = 0; c < NCH; c++) {
        int buf = c & 1;
        if (c + 1 < NCH) {
            load_chunk((c + 1) * KCH, buf ^ 1);
            asm volatile("cp.async.wait_group 1;\n");
        } else {
            asm volatile("cp.async.wait_group 0;\n");
        }
        __syncthreads();

#pragma unroll
        for (int ks = 0; ks < KCH; ks += 8) {
            unsigned a[2][4], b[8][2];
#pragma unroll
            for (int mi = 0; mi < 2; mi++) {
                int r0 = wm * 32 + mi * 16 + g;
                a[mi][0] = f2tf32(Af[buf][r0][ks + tg]);
                a[mi][1] = f2tf32(Af[buf][r0 + 8][ks + tg]);
                a[mi][2] = f2tf32(Af[buf][r0][ks + tg + 4]);
                a[mi][3] = f2tf32(Af[buf][r0 + 8][ks + tg + 4]);
            }
#pragma unroll
            for (int ni = 0; ni < 8; ni++) {
                int n = wn * 64 + ni * 8 + g;
                b[ni][0] = f2tf32(Bf[buf][ks + tg][n]);
                b[ni][1] = f2tf32(Bf[buf][ks + tg + 4][n]);
            }
#pragma unroll
            for (int mi = 0; mi < 2; mi++)
#pragma unroll
                for (int ni = 0; ni < 8; ni++)
                    mma_tf32(acc[mi][ni], a[mi], b[ni]);
        }
        __syncthreads();
    }

    // ---- epilogue: + bias, store fp32
#pragma unroll
    for (int mi = 0; mi < 2; mi++) {
        int r = row0 + wm * 32 + mi * 16 + g;
#pragma unroll
        for (int ni = 0; ni < 8; ni++) {
            int cb = wn * 64 + ni * 8 + tg * 2;
            float b0 = bias[cb], b1 = bias[cb + 1];
            if (r < M) {
                float2 o = make_float2(acc[mi][ni][0] + b0, acc[mi][ni][1] + b1);
                *(float2*)(C + (size_t)r * D_OUT + cb) = o;
            }
            if (r + 8 < M) {
                float2 o = make_float2(acc[mi][ni][2] + b0, acc[mi][ni][3] + b1);
                *(float2*)(C + (size_t)(r + 8) * D_OUT + cb) = o;
            }
        }
    }
}

// ---------------------------------------------------------------------------
// Kernel 6a: warp-per-node aggregation for word + doc nodes (short segments)
// ---------------------------------------------------------------------------
__device__ __forceinline__ void seg_mean_acc(int et, int d, int lane, float4& res) {
    const int*   off = off_ptr(et);
    const uint2* pp  = pair_ptr(et);
    const float* Wh  = Wh_ptr(et);
    int beg = off[d], end = off[d + 1];
    float4 acc0 = make_float4(0.f, 0.f, 0.f, 0.f);
    float4 acc1 = make_float4(0.f, 0.f, 0.f, 0.f);
    int j = beg;
    for (; j + 4 <= end; j += 4) {
        uint2 p0 = pp[j],   p1 = pp[j+1], p2 = pp[j+2], p3 = pp[j+3];
        float w0 = __uint_as_float(p0.y), w1 = __uint_as_float(p1.y);
        float w2 = __uint_as_float(p2.y), w3 = __uint_as_float(p3.y);
        float4 v0 = *(const float4*)(Wh + (size_t)p0.x * D_OUT + lane * 4);
        float4 v1 = *(const float4*)(Wh + (size_t)p1.x * D_OUT + lane * 4);
        float4 v2 = *(const float4*)(Wh + (size_t)p2.x * D_OUT + lane * 4);
        float4 v3 = *(const float4*)(Wh + (size_t)p3.x * D_OUT + lane * 4);
        acc0.x = fmaf(w0, v0.x, acc0.x); acc0.y = fmaf(w0, v0.y, acc0.y);
        acc0.z = fmaf(w0, v0.z, acc0.z); acc0.w = fmaf(w0, v0.w, acc0.w);
        acc1.x = fmaf(w1, v1.x, acc1.x); acc1.y = fmaf(w1, v1.y, acc1.y);
        acc1.z = fmaf(w1, v1.z, acc1.z); acc1.w = fmaf(w1, v1.w, acc1.w);
        acc0.x = fmaf(w2, v2.x, acc0.x); acc0.y = fmaf(w2, v2.y, acc0.y);
        acc0.z = fmaf(w2, v2.z, acc0.z); acc0.w = fmaf(w2, v2.w, acc0.w);
        acc1.x = fmaf(w3, v3.x, acc1.x); acc1.y = fmaf(w3, v3.y, acc1.y);
        acc1.z = fmaf(w3, v3.z, acc1.z); acc1.w = fmaf(w3, v3.w, acc1.w);
    }
    for (; j < end; j++) {
        uint2 p = pp[j];
        float w = __uint_as_float(p.y);
        float4 v = *(const float4*)(Wh + (size_t)p.x * D_OUT + lane * 4);
        acc0.x = fmaf(w, v.x, acc0.x); acc0.y = fmaf(w, v.y, acc0.y);
        acc0.z = fmaf(w, v.z, acc0.z); acc0.w = fmaf(w, v.w, acc0.w);
    }
    float inv = 1.0f / fmaxf((float)(end - beg), 1.0f);
    res.x += (acc0.x + acc1.x) * inv;
    res.y += (acc0.y + acc1.y) * inv;
    res.z += (acc0.z + acc1.z) * inv;
    res.w += (acc0.w + acc1.w) * inv;
}

__global__ void agg_wd_kernel(float* __restrict__ out) {
    int gw   = (blockIdx.x * blockDim.x + threadIdx.x) >> 5;
    int lane = threadIdx.x & 31;
    if (gw >= N_WD) return;
    float4 res = make_float4(0.f, 0.f, 0.f, 0.f);
    size_t orow;
    if (gw < N_WORD) {
        seg_mean_acc(0, gw, lane, res);
        orow = gw;
    } else {
        int d = gw - N_WORD;
        seg_mean_acc(2, d, lane, res);
        seg_mean_acc(3, d, lane, res);
        orow = (size_t)(N_WORD + N_TOPIC) + d;
    }
    *(float4*)(out + orow * D_OUT + lane * 4) = res;
}

// ---------------------------------------------------------------------------
// Kernel 6b: block-per-node aggregation for topic nodes (long segments).
// 8 warps stride the segment; cross-warp reduce via smem.
// ---------------------------------------------------------------------------
__global__ void __launch_bounds__(256) agg_topic_kernel(float* __restrict__ out) {
    __shared__ float4 sm[8][32];
    const int d    = blockIdx.x;            // topic node
    const int lane = threadIdx.x & 31;
    const int wid  = threadIdx.x >> 5;
    float4 res = make_float4(0.f, 0.f, 0.f, 0.f);

#pragma unroll
    for (int pass = 0; pass < 2; pass++) {
        const int    et  = pass ? 4 : 1;
        const int*   off = off_ptr(et);
        const uint2* pp  = pair_ptr(et);
        const float* Wh  = Wh_ptr(et);
        int beg = off[d], end = off[d + 1];
        float4 acc = make_float4(0.f, 0.f, 0.f, 0.f);
        int j = beg + wid;
        // 2-wide software pipeline over stride-8 walk
        for (; j + 8 < end; j += 16) {
            uint2 pA = pp[j], pB = pp[j + 8];
            float wA = __uint_as_float(pA.y), wB = __uint_as_float(pB.y);
            float4 vA = *(const float4*)(Wh + (size_t)pA.x * D_OUT + lane * 4);
            float4 vB = *(const float4*)(Wh + (size_t)pB.x * D_OUT + lane * 4);
            acc.x = fmaf(wA, vA.x, acc.x); acc.y = fmaf(wA, vA.y, acc.y);
            acc.z = fmaf(wA, vA.z, acc.z); acc.w = fmaf(wA, vA.w, acc.w);
            acc.x = fmaf(wB, vB.x, acc.x); acc.y = fmaf(wB, vB.y, acc.y);
            acc.z = fmaf(wB, vB.z, acc.z); acc.w = fmaf(wB, vB.w, acc.w);
        }
        if (j < end) {
            uint2 p = pp[j];
            float w = __uint_as_float(p.y);
            float4 v = *(const float4*)(Wh + (size_t)p.x * D_OUT + lane * 4);
            acc.x = fmaf(w, v.x, acc.x); acc.y = fmaf(w, v.y, acc.y);
            acc.z = fmaf(w, v.z, acc.z); acc.w = fmaf(w, v.w, acc.w);
        }
        sm[wid][lane] = acc;
        __syncthreads();
        if (wid == 0) {
            float4 s = sm[0][lane];
#pragma unroll
            for (int w2 = 1; w2 < 8; w2++) {
                float4 t = sm[w2][lane];
                s.x += t.x; s.y += t.y; s.z += t.z; s.w += t.w;
            }
            float inv = 1.0f / fmaxf((float)(end - beg), 1.0f);
            res.x += s.x * inv; res.y += s.y * inv;
            res.z += s.z * inv; res.w += s.w * inv;
        }
        __syncthreads();
    }
    if (wid == 0)
        *(float4*)(out + (size_t)(N_WORD + d) * D_OUT + lane * 4) = res;
}

// ---------------------------------------------------------------------------
// Launch: GEMM + topic-agg on side stream, CSR build + word/doc agg on main.
// ---------------------------------------------------------------------------
extern "C" void kernel_launch(void* const* d_in, const int* in_sizes, int n_in,
                              void* d_out, int out_size) {
    (void)out_size;

    static cudaStream_t s_side = nullptr;
    static cudaEvent_t  ev_fork = nullptr, ev_join = nullptr,
                        ev_fill = nullptr, ev_side = nullptr;
    if (!s_side) {
        cudaStreamCreateWithFlags(&s_side, cudaStreamNonBlocking);
        cudaEventCreateWithFlags(&ev_fork, cudaEventDisableTiming);
        cudaEventCreateWithFlags(&ev_join, cudaEventDisableTiming);
        cudaEventCreateWithFlags(&ev_fill, cudaEventDisableTiming);
        cudaEventCreateWithFlags(&ev_side, cudaEventDisableTiming);
    }

    // Resolve input ordering (W matrices are 38400 elems)
    int iS[5], iD[5], iW_[5], iWm[5], iB[5];
    bool interleaved = (n_in >= 7 && in_sizes[5] == D_IN * D_OUT);
    for (int et = 0; et < 5; et++) {
        if (interleaved) {
            int base = 2 + et * 5;
            iS[et] = base; iD[et] = base + 1; iW_[et] = base + 2;
            iWm[et] = base + 3; iB[et] = base + 4;
        } else {
            iS[et] = 2 + et * 3; iD[et] = 3 + et * 3; iW_[et] = 4 + et * 3;
            iWm[et] = 17 + et * 2; iB[et] = 18 + et * 2;
        }
    }

    EdgeArgs ea;
    GemmArgs ga;
    ga.featW = (const float*)d_in[0];
    ga.featT = (const float*)d_in[1];
    for (int et = 0; et < 5; et++) {
        ea.src[et]  = (const int*)d_in[iS[et]];
        ea.dst[et]  = (const int*)d_in[iD[et]];
        ea.w[et]    = (const float*)d_in[iW_[et]];
        ga.Wm[et]   = (const float*)d_in[iWm[et]];
        ga.bias[et] = (const float*)d_in[iB[et]];
    }
    float* out = (float*)d_out;

    // Fork: GEMM on side stream (independent of CSR build)
    cudaEventRecord(ev_fork, 0);
    cudaStreamWaitEvent(s_side, ev_fork, 0);
    gemm_tf32_kernel<<<TILES_TOTAL, 256, 0, s_side>>>(ga);
    cudaEventRecord(ev_join, s_side);

    // Main stream: CSR build
    zero_deg_kernel<<<dim3((N_WORD + 255) / 256, 5), 256>>>();
    hist_all_kernel<<<(E_TOT + 255) / 256, 256>>>(ea);
    scan_all_kernel<<<5, 1024>>>();
    fill_all_kernel<<<(E_TOT + 255) / 256, 256>>>(ea);
    cudaEventRecord(ev_fill, 0);

    // Side stream: topic aggregation (gemm already done in-order; wait for fill)
    cudaStreamWaitEvent(s_side, ev_fill, 0);
    agg_topic_kernel<<<N_TOPIC, 256, 0, s_side>>>(out);
    cudaEventRecord(ev_side, s_side);

    // Main stream: word+doc aggregation (needs gemm join), then join side
    cudaStreamWaitEvent(0, ev_join, 0);
    agg_wd_kernel<<<(N_WD * 32 + 255) / 256, 256>>>(out);
    cudaStreamWaitEvent(0, ev_side, 0);
}

// round 11
// speedup vs baseline: 1.0651x; 1.0651x over previous
#include <cuda_runtime.h>
#include <cstdint>

// ---------------------------------------------------------------------------
// Problem constants
// ---------------------------------------------------------------------------
#define N_WORD   30000
#define N_TOPIC  1000
#define N_DOC    15000
#define D_IN     300
#define D_OUT    128

#define E_WW 800000
#define E_WT 400000
#define E_WD 600000
#define E_TD 300000
#define E_TT 150000
#define E_TOT (E_WW + E_WT + E_WD + E_TD + E_TT)   // 2,250,000
// etype ids: 0=ww, 1=wt, 2=wd, 3=td, 4=tt
// NOTE: all etype boundaries are divisible by 4 -> 4-edge groups never straddle.

#define N_WD (N_WORD + N_DOC)                      // 45,000 warp-per-node nodes
#define N_NODES_TOT (N_WORD + N_TOPIC + N_DOC + N_DOC + N_TOPIC)  // 62,000 deg slots

// GEMM tile bookkeeping: 128-row tiles per etype
#define T_W  235   // ceil(30000/128)
#define T_T  8     // ceil(1000/128)
#define TILES_TOTAL (3 * T_W + 2 * T_T)            // 721
#define KCH  32
#define NCH  10    // ceil(300/32) -> padded K=320

// ---------------------------------------------------------------------------
// Static device scratch (no allocation allowed)
// ---------------------------------------------------------------------------
__device__ float g_Wh_ww[(size_t)N_WORD  * D_OUT];
__device__ float g_Wh_wt[(size_t)N_WORD  * D_OUT];
__device__ float g_Wh_wd[(size_t)N_WORD  * D_OUT];
__device__ float g_Wh_td[(size_t)N_TOPIC * D_OUT];
__device__ float g_Wh_tt[(size_t)N_TOPIC * D_OUT];

__device__ __align__(16) int g_deg_ww[N_WORD];  __device__ int g_off_ww[N_WORD + 1];
__device__ __align__(16) int g_deg_wt[N_TOPIC]; __device__ int g_off_wt[N_TOPIC + 1];
__device__ __align__(16) int g_deg_wd[N_DOC];   __device__ int g_off_wd[N_DOC + 1];
__device__ __align__(16) int g_deg_td[N_DOC];   __device__ int g_off_td[N_DOC + 1];
__device__ __align__(16) int g_deg_tt[N_TOPIC]; __device__ int g_off_tt[N_TOPIC + 1];

// per-edge rank within its dst bucket (flat over all etypes)
__device__ __align__(16) int g_rank[E_TOT];

// dst-sorted packed (src, w) pairs
__device__ uint2 g_pair_ww[E_WW];
__device__ uint2 g_pair_wt[E_WT];
__device__ uint2 g_pair_wd[E_WD];
__device__ uint2 g_pair_td[E_TD];
__device__ uint2 g_pair_tt[E_TT];

__device__ __forceinline__ float* Wh_ptr(int et) {
    switch (et) { case 0: return g_Wh_ww; case 1: return g_Wh_wt; case 2: return g_Wh_wd;
                  case 3: return g_Wh_td; default: return g_Wh_tt; }
}
__device__ __forceinline__ int* deg_ptr(int et) {
    switch (et) { case 0: return g_deg_ww; case 1: return g_deg_wt; case 2: return g_deg_wd;
                  case 3: return g_deg_td; default: return g_deg_tt; }
}
__device__ __forceinline__ int* off_ptr(int et) {
    switch (et) { case 0: return g_off_ww; case 1: return g_off_wt; case 2: return g_off_wd;
                  case 3: return g_off_td; default: return g_off_tt; }
}
__device__ __forceinline__ uint2* pair_ptr(int et) {
    switch (et) { case 0: return g_pair_ww; case 1: return g_pair_wt; case 2: return g_pair_wd;
                  case 3: return g_pair_td; default: return g_pair_tt; }
}
__device__ __forceinline__ int ndst_of(int et) {
    switch (et) { case 0: return N_WORD; case 1: return N_TOPIC; case 2: return N_DOC;
                  case 3: return N_DOC; default: return N_TOPIC; }
}

// ---------------------------------------------------------------------------
// Pointer bundles
// ---------------------------------------------------------------------------
struct EdgeArgs {
    const int*   src[5];
    const int*   dst[5];
    const float* w[5];
};
struct GemmArgs {
    const float* featW;
    const float* featT;
    const float* Wm[5];
    const float* bias[5];
};

// flat-edge -> (etype, local index)
__device__ __forceinline__ void edge_map(int i, int& et, int& j) {
    if (i < E_WW)                        { et = 0; j = i; }
    else if (i < E_WW + E_WT)            { et = 1; j = i - E_WW; }
    else if (i < E_WW + E_WT + E_WD)     { et = 2; j = i - (E_WW + E_WT); }
    else if (i < E_TOT - E_TT)           { et = 3; j = i - (E_WW + E_WT + E_WD); }
    else                                 { et = 4; j = i - (E_TOT - E_TT); }
}

// ---------------------------------------------------------------------------
// Kernel 2: fused histogram, 4 edges/thread (int4 loads, int4 rank store).
// atomicAdd return value = per-edge rank within its dst bucket.
// deg[] was zeroed by the previous call's fill_all (module init on call 0).
// ---------------------------------------------------------------------------
__global__ void hist_all_kernel(EdgeArgs ea) {
    int i4 = (blockIdx.x * blockDim.x + threadIdx.x) * 4;
    if (i4 >= E_TOT) return;
    int et, j; edge_map(i4, et, j);
    int* deg = deg_ptr(et);
    int4 d4 = *(const int4*)(ea.dst[et] + j);
    int4 r4;
    r4.x = atomicAdd(&deg[d4.x], 1);
    r4.y = atomicAdd(&deg[d4.y], 1);
    r4.z = atomicAdd(&deg[d4.z], 1);
    r4.w = atomicAdd(&deg[d4.w], 1);
    *(int4*)(g_rank + i4) = r4;
}

// ---------------------------------------------------------------------------
// Kernel 3: fused scan, one block per etype. Warp-shuffle scan (2 barriers),
// int4 partial sums.
// ---------------------------------------------------------------------------
__global__ void scan_all_kernel() {
    const int et = blockIdx.x;
    const int n = ndst_of(et);
    int* deg = deg_ptr(et);
    int* off = off_ptr(et);
    __shared__ int warp_pre[32];
    __shared__ int s_total;

    const int t = threadIdx.x;
    const int lane = t & 31, wid = t >> 5;
    // chunk rounded up to 4 so int4 loads stay aligned
    int chunk = (((n + 1023) >> 10) + 3) & ~3;
    int beg = t * chunk;
    int end = min(beg + chunk, n);

    int s = 0;
    int i = beg;
    for (; i + 4 <= end; i += 4) {
        int4 v = *(const int4*)(deg + i);
        s += v.x + v.y + v.z + v.w;
    }
    for (; i < end; i++) s += deg[i];

    // warp-inclusive scan of per-thread sums
    int inc = s;
#pragma unroll
    for (int d = 1; d < 32; d <<= 1) {
        int v = __shfl_up_sync(0xFFFFFFFFu, inc, d);
        if (lane >= d) inc += v;
    }
    if (lane == 31) warp_pre[wid] = inc;
    __syncthreads();
    if (wid == 0) {
        int ws = warp_pre[lane];
        int winc = ws;
#pragma unroll
        for (int d = 1; d < 32; d <<= 1) {
            int v = __shfl_up_sync(0xFFFFFFFFu, winc, d);
            if (lane >= d) winc += v;
        }
        warp_pre[lane] = winc - ws;         // exclusive warp prefix
        if (lane == 31) s_total = winc;
    }
    __syncthreads();

    int run = warp_pre[wid] + (inc - s);    // exclusive prefix for this thread
    for (int j2 = beg; j2 < end; j2++) {
        off[j2] = run;
        run += deg[j2];
    }
    if (t == 0) off[n] = s_total;
}

// ---------------------------------------------------------------------------
// Kernel 4: atomic-free fill, 4 edges/thread. Also re-zeroes deg[] (dead after
// scan) so the next call needs no separate zeroing kernel.
// ---------------------------------------------------------------------------
__global__ void fill_all_kernel(EdgeArgs ea) {
    int gid = blockIdx.x * blockDim.x + threadIdx.x;

    // re-zero one deg slot per thread (62,000 slots << 562,500 threads)
    if (gid < N_NODES_TOT) {
        int k = gid;
        if      (k < N_WORD)                       g_deg_ww[k] = 0;
        else if (k < N_WORD + N_TOPIC)             g_deg_wt[k - N_WORD] = 0;
        else if (k < N_WORD + N_TOPIC + N_DOC)     g_deg_wd[k - (N_WORD + N_TOPIC)] = 0;
        else if (k < N_NODES_TOT - N_TOPIC)        g_deg_td[k - (N_WORD + N_TOPIC + N_DOC)] = 0;
        else                                       g_deg_tt[k - (N_NODES_TOT - N_TOPIC)] = 0;
    }

    int i4 = gid * 4;
    if (i4 >= E_TOT) return;
    int et, j; edge_map(i4, et, j);
    const int* off = off_ptr(et);
    uint2* pp = pair_ptr(et);
    int4   s4 = *(const int4*)(ea.src[et] + j);
    int4   d4 = *(const int4*)(ea.dst[et] + j);
    float4 w4 = *(const float4*)(ea.w[et] + j);
    int4   r4 = *(const int4*)(g_rank + i4);

    pp[off[d4.x] + r4.x] = make_uint2((unsigned)s4.x, __float_as_uint(w4.x));
    pp[off[d4.y] + r4.y] = make_uint2((unsigned)s4.y, __float_as_uint(w4.y));
    pp[off[d4.z] + r4.z] = make_uint2((unsigned)s4.z, __float_as_uint(w4.z));
    pp[off[d4.w] + r4.w] = make_uint2((unsigned)s4.w, __float_as_uint(w4.w));
}

// ---------------------------------------------------------------------------
// Kernel 5: fused tf32 GEMM with cp.async double buffering.
// ---------------------------------------------------------------------------
__device__ __forceinline__ unsigned f2tf32(float x) {
    unsigned u; asm("cvt.rna.tf32.f32 %0, %1;" : "=r"(u) : "f"(x)); return u;
}
__device__ __forceinline__ void mma_tf32(float* c, const unsigned* a, const unsigned* b) {
    asm volatile(
        "mma.sync.aligned.m16n8k8.row.col.f32.tf32.tf32.f32 "
        "{%0,%1,%2,%3}, {%4,%5,%6,%7}, {%8,%9}, {%0,%1,%2,%3};\n"
        : "+f"(c[0]), "+f"(c[1]), "+f"(c[2]), "+f"(c[3])
        : "r"(a[0]), "r"(a[1]), "r"(a[2]), "r"(a[3]), "r"(b[0]), "r"(b[1]));
}
__device__ __forceinline__ void cp_async16(void* smem, const void* gmem, int valid_bytes) {
    unsigned sa = (unsigned)__cvta_generic_to_shared(smem);
    asm volatile("cp.async.cg.shared.global [%0], [%1], 16, %2;\n"
                 :: "r"(sa), "l"(gmem), "r"(valid_bytes));
}

__global__ void __launch_bounds__(256, 2)
gemm_tf32_kernel(GemmArgs ga) {
    __shared__ float Af[2][128][36];    // [buf][row][k]
    __shared__ float Bf[2][32][136];    // [buf][k][n]

    int bt = blockIdx.x;
    int et, tile;
    if      (bt < T_W)                 { et = 0; tile = bt; }
    else if (bt < 2 * T_W)             { et = 1; tile = bt - T_W; }
    else if (bt < 3 * T_W)             { et = 2; tile = bt - 2 * T_W; }
    else if (bt < 3 * T_W + T_T)       { et = 3; tile = bt - 3 * T_W; }
    else                               { et = 4; tile = bt - (3 * T_W + T_T); }

    const float* A    = (et < 3) ? ga.featW : ga.featT;
    const int    M    = (et < 3) ? N_WORD : N_TOPIC;
    const float* Wm   = ga.Wm[et];
    const float* bias = ga.bias[et];
    float*       C    = Wh_ptr(et);

    const int row0 = tile * 128;
    const int tid  = threadIdx.x;
    const int lane = tid & 31, wid = tid >> 5;
    const int wm = wid & 3, wn = wid >> 2;       // warp grid 4 x 2
    const int g  = lane >> 2, tg = lane & 3;     // groupID / thread-in-group

    float acc[2][8][4];
#pragma unroll
    for (int mi = 0; mi < 2; mi++)
#pragma unroll
        for (int ni = 0; ni < 8; ni++)
#pragma unroll
            for (int q = 0; q < 4; q++) acc[mi][ni][q] = 0.0f;

    auto load_chunk = [&](int k0, int buf) {
#pragma unroll
        for (int it = 0; it < 4; it++) {
            int slot = it * 256 + tid;           // 0..1023
            int r = slot >> 3, kq = slot & 7;
            int gr = row0 + r, gk = k0 + kq * 4;
            int ok = (gr < M && gk + 4 <= D_IN);
            const float* gp = A + (size_t)(ok ? gr : 0) * D_IN + (ok ? gk : 0);
            cp_async16(&Af[buf][r][kq * 4], gp, ok ? 16 : 0);
        }
#pragma unroll
        for (int it = 0; it < 4; it++) {
            int slot = it * 256 + tid;           // 0..1023
            int kk = slot >> 5, cq = slot & 31;
            int gk = k0 + kk;
            int ok = (gk < D_IN);
            const float* gp = Wm + (size_t)(ok ? gk : 0) * D_OUT + cq * 4;
            cp_async16(&Bf[buf][kk][cq * 4], gp, ok ? 16 : 0);
        }
        asm volatile("cp.async.commit_group;\n");
    };

    load_chunk(0, 0);
    for (int c = 0; c < NCH; c++) {
        int buf = c & 1;
        if (c + 1 < NCH) {
            load_chunk((c + 1) * KCH, buf ^ 1);
            asm volatile("cp.async.wait_group 1;\n");
        } else {
            asm volatile("cp.async.wait_group 0;\n");
        }
        __syncthreads();

#pragma unroll
        for (int ks = 0; ks < KCH; ks += 8) {
            unsigned a[2][4], b[8][2];
#pragma unroll
            for (int mi = 0; mi < 2; mi++) {
                int r0 = wm * 32 + mi * 16 + g;
                a[mi][0] = f2tf32(Af[buf][r0][ks + tg]);
                a[mi][1] = f2tf32(Af[buf][r0 + 8][ks + tg]);
                a[mi][2] = f2tf32(Af[buf][r0][ks + tg + 4]);
                a[mi][3] = f2tf32(Af[buf][r0 + 8][ks + tg + 4]);
            }
#pragma unroll
            for (int ni = 0; ni < 8; ni++) {
                int n = wn * 64 + ni * 8 + g;
                b[ni][0] = f2tf32(Bf[buf][ks + tg][n]);
                b[ni][1] = f2tf32(Bf[buf][ks + tg + 4][n]);
            }
#pragma unroll
            for (int mi = 0; mi < 2; mi++)
#pragma unroll
                for (int ni = 0; ni < 8; ni++)
                    mma_tf32(acc[mi][ni], a[mi], b[ni]);
        }
        __syncthreads();
    }

#pragma unroll
    for (int mi = 0; mi < 2; mi++) {
        int r = row0 + wm * 32 + mi * 16 + g;
#pragma unroll
        for (int ni = 0; ni < 8; ni++) {
            int cb = wn * 64 + ni * 8 + tg * 2;
            float b0 = bias[cb], b1 = bias[cb + 1];
            if (r < M) {
                float2 o = make_float2(acc[mi][ni][0] + b0, acc[mi][ni][1] + b1);
                *(float2*)(C + (size_t)r * D_OUT + cb) = o;
            }
            if (r + 8 < M) {
                float2 o = make_float2(acc[mi][ni][2] + b0, acc[mi][ni][3] + b1);
                *(float2*)(C + (size_t)(r + 8) * D_OUT + cb) = o;
            }
        }
    }
}

// ---------------------------------------------------------------------------
// Kernel 6a: warp-per-node aggregation for word + doc nodes
// ---------------------------------------------------------------------------
__device__ __forceinline__ void seg_mean_acc(int et, int d, int lane, float4& res) {
    const int*   off = off_ptr(et);
    const uint2* pp  = pair_ptr(et);
    const float* Wh  = Wh_ptr(et);
    int beg = off[d], end = off[d + 1];
    float4 acc0 = make_float4(0.f, 0.f, 0.f, 0.f);
    float4 acc1 = make_float4(0.f, 0.f, 0.f, 0.f);
    int j = beg;
    for (; j + 4 <= end; j += 4) {
        uint2 p0 = pp[j],   p1 = pp[j+1], p2 = pp[j+2], p3 = pp[j+3];
        float w0 = __uint_as_float(p0.y), w1 = __uint_as_float(p1.y);
        float w2 = __uint_as_float(p2.y), w3 = __uint_as_float(p3.y);
        float4 v0 = *(const float4*)(Wh + (size_t)p0.x * D_OUT + lane * 4);
        float4 v1 = *(const float4*)(Wh + (size_t)p1.x * D_OUT + lane * 4);
        float4 v2 = *(const float4*)(Wh + (size_t)p2.x * D_OUT + lane * 4);
        float4 v3 = *(const float4*)(Wh + (size_t)p3.x * D_OUT + lane * 4);
        acc0.x = fmaf(w0, v0.x, acc0.x); acc0.y = fmaf(w0, v0.y, acc0.y);
        acc0.z = fmaf(w0, v0.z, acc0.z); acc0.w = fmaf(w0, v0.w, acc0.w);
        acc1.x = fmaf(w1, v1.x, acc1.x); acc1.y = fmaf(w1, v1.y, acc1.y);
        acc1.z = fmaf(w1, v1.z, acc1.z); acc1.w = fmaf(w1, v1.w, acc1.w);
        acc0.x = fmaf(w2, v2.x, acc0.x); acc0.y = fmaf(w2, v2.y, acc0.y);
        acc0.z = fmaf(w2, v2.z, acc0.z); acc0.w = fmaf(w2, v2.w, acc0.w);
        acc1.x = fmaf(w3, v3.x, acc1.x); acc1.y = fmaf(w3, v3.y, acc1.y);
        acc1.z = fmaf(w3, v3.z, acc1.z); acc1.w = fmaf(w3, v3.w, acc1.w);
    }
    for (; j < end; j++) {
        uint2 p = pp[j];
        float w = __uint_as_float(p.y);
        float4 v = *(const float4*)(Wh + (size_t)p.x * D_OUT + lane * 4);
        acc0.x = fmaf(w, v.x, acc0.x); acc0.y = fmaf(w, v.y, acc0.y);
        acc0.z = fmaf(w, v.z, acc0.z); acc0.w = fmaf(w, v.w, acc0.w);
    }
    float inv = 1.0f / fmaxf((float)(end - beg), 1.0f);
    res.x += (acc0.x + acc1.x) * inv;
    res.y += (acc0.y + acc1.y) * inv;
    res.z += (acc0.z + acc1.z) * inv;
    res.w += (acc0.w + acc1.w) * inv;
}

__global__ void agg_wd_kernel(float* __restrict__ out) {
    int gw   = (blockIdx.x * blockDim.x + threadIdx.x) >> 5;
    int lane = threadIdx.x & 31;
    if (gw >= N_WD) return;
    float4 res = make_float4(0.f, 0.f, 0.f, 0.f);
    size_t orow;
    if (gw < N_WORD) {
        seg_mean_acc(0, gw, lane, res);
        orow = gw;
    } else {
        int d = gw - N_WORD;
        seg_mean_acc(2, d, lane, res);
        seg_mean_acc(3, d, lane, res);
        orow = (size_t)(N_WORD + N_TOPIC) + d;
    }
    *(float4*)(out + orow * D_OUT + lane * 4) = res;
}

// ---------------------------------------------------------------------------
// Kernel 6b: block-per-node aggregation for topic nodes (long segments)
// ---------------------------------------------------------------------------
__global__ void __launch_bounds__(256) agg_topic_kernel(float* __restrict__ out) {
    __shared__ float4 sm[8][32];
    const int d    = blockIdx.x;
    const int lane = threadIdx.x & 31;
    const int wid  = threadIdx.x >> 5;
    float4 res = make_float4(0.f, 0.f, 0.f, 0.f);

#pragma unroll
    for (int pass = 0; pass < 2; pass++) {
        const int    et  = pass ? 4 : 1;
        const int*   off = off_ptr(et);
        const uint2* pp  = pair_ptr(et);
        const float* Wh  = Wh_ptr(et);
        int beg = off[d], end = off[d + 1];
        float4 acc = make_float4(0.f, 0.f, 0.f, 0.f);
        int j = beg + wid;
        for (; j + 8 < end; j += 16) {
            uint2 pA = pp[j], pB = pp[j + 8];
            float wA = __uint_as_float(pA.y), wB = __uint_as_float(pB.y);
            float4 vA = *(const float4*)(Wh + (size_t)pA.x * D_OUT + lane * 4);
            float4 vB = *(const float4*)(Wh + (size_t)pB.x * D_OUT + lane * 4);
            acc.x = fmaf(wA, vA.x, acc.x); acc.y = fmaf(wA, vA.y, acc.y);
            acc.z = fmaf(wA, vA.z, acc.z); acc.w = fmaf(wA, vA.w, acc.w);
            acc.x = fmaf(wB, vB.x, acc.x); acc.y = fmaf(wB, vB.y, acc.y);
            acc.z = fmaf(wB, vB.z, acc.z); acc.w = fmaf(wB, vB.w, acc.w);
        }
        if (j < end) {
            uint2 p = pp[j];
            float w = __uint_as_float(p.y);
            float4 v = *(const float4*)(Wh + (size_t)p.x * D_OUT + lane * 4);
            acc.x = fmaf(w, v.x, acc.x); acc.y = fmaf(w, v.y, acc.y);
            acc.z = fmaf(w, v.z, acc.z); acc.w = fmaf(w, v.w, acc.w);
        }
        sm[wid][lane] = acc;
        __syncthreads();
        if (wid == 0) {
            float4 s = sm[0][lane];
#pragma unroll
            for (int w2 = 1; w2 < 8; w2++) {
                float4 t = sm[w2][lane];
                s.x += t.x; s.y += t.y; s.z += t.z; s.w += t.w;
            }
            float inv = 1.0f / fmaxf((float)(end - beg), 1.0f);
            res.x += s.x * inv; res.y += s.y * inv;
            res.z += s.z * inv; res.w += s.w * inv;
        }
        __syncthreads();
    }
    if (wid == 0)
        *(float4*)(out + (size_t)(N_WORD + d) * D_OUT + lane * 4) = res;
}

// ---------------------------------------------------------------------------
// Launch: GEMM + topic-agg on side stream, CSR build + word/doc agg on main.
// ---------------------------------------------------------------------------
extern "C" void kernel_launch(void* const* d_in, const int* in_sizes, int n_in,
                              void* d_out, int out_size) {
    (void)out_size;

    static cudaStream_t s_side = nullptr;
    static cudaEvent_t  ev_fork = nullptr, ev_join = nullptr,
                        ev_fill = nullptr, ev_side = nullptr;
    if (!s_side) {
        cudaStreamCreateWithFlags(&s_side, cudaStreamNonBlocking);
        cudaEventCreateWithFlags(&ev_fork, cudaEventDisableTiming);
        cudaEventCreateWithFlags(&ev_join, cudaEventDisableTiming);
        cudaEventCreateWithFlags(&ev_fill, cudaEventDisableTiming);
        cudaEventCreateWithFlags(&ev_side, cudaEventDisableTiming);
    }

    // Resolve input ordering (W matrices are 38400 elems)
    int iS[5], iD[5], iW_[5], iWm[5], iB[5];
    bool interleaved = (n_in >= 7 && in_sizes[5] == D_IN * D_OUT);
    for (int et = 0; et < 5; et++) {
        if (interleaved) {
            int base = 2 + et * 5;
            iS[et] = base; iD[et] = base + 1; iW_[et] = base + 2;
            iWm[et] = base + 3; iB[et] = base + 4;
        } else {
            iS[et] = 2 + et * 3; iD[et] = 3 + et * 3; iW_[et] = 4 + et * 3;
            iWm[et] = 17 + et * 2; iB[et] = 18 + et * 2;
        }
    }

    EdgeArgs ea;
    GemmArgs ga;
    ga.featW = (const float*)d_in[0];
    ga.featT = (const float*)d_in[1];
    for (int et = 0; et < 5; et++) {
        ea.src[et]  = (const int*)d_in[iS[et]];
        ea.dst[et]  = (const int*)d_in[iD[et]];
        ea.w[et]    = (const float*)d_in[iW_[et]];
        ga.Wm[et]   = (const float*)d_in[iWm[et]];
        ga.bias[et] = (const float*)d_in[iB[et]];
    }
    float* out = (float*)d_out;

    // Fork: GEMM on side stream (independent of CSR build)
    cudaEventRecord(ev_fork, 0);
    cudaStreamWaitEvent(s_side, ev_fork, 0);
    gemm_tf32_kernel<<<TILES_TOTAL, 256, 0, s_side>>>(ga);
    cudaEventRecord(ev_join, s_side);

    // Main stream: CSR build (deg zeroed by previous call's fill / module init)
    hist_all_kernel<<<(E_TOT / 4 + 255) / 256, 256>>>(ea);
    scan_all_kernel<<<5, 1024>>>();
    fill_all_kernel<<<(E_TOT / 4 + 255) / 256, 256>>>(ea);
    cudaEventRecord(ev_fill, 0);

    // Side stream: topic aggregation (after gemm in-order; wait for fill)
    cudaStreamWaitEvent(s_side, ev_fill, 0);
    agg_topic_kernel<<<N_TOPIC, 256, 0, s_side>>>(out);
    cudaEventRecord(ev_side, s_side);

    // Main stream: word+doc aggregation (needs gemm join), then join side
    cudaStreamWaitEvent(0, ev_join, 0);
    agg_wd_kernel<<<(N_WD * 32 + 255) / 256, 256>>>(out);
    cudaStreamWaitEvent(0, ev_side, 0);
}

// round 12
// speedup vs baseline: 1.0999x; 1.0327x over previous
#include <cuda_runtime.h>
#include <cuda_fp16.h>
#include <cstdint>

// ---------------------------------------------------------------------------
// Problem constants
// ---------------------------------------------------------------------------
#define N_WORD   30000
#define N_TOPIC  1000
#define N_DOC    15000
#define D_IN     300
#define D_OUT    128

#define E_WW 800000
#define E_WT 400000
#define E_WD 600000
#define E_TD 300000
#define E_TT 150000
#define E_TOT (E_WW + E_WT + E_WD + E_TD + E_TT)   // 2,250,000
// etype ids: 0=ww, 1=wt, 2=wd, 3=td, 4=tt
// NOTE: all etype boundaries are divisible by 4 -> 4-edge groups never straddle.

#define N_WD (N_WORD + N_DOC)                      // 45,000 warp-per-node nodes
#define N_NODES_TOT (N_WORD + N_TOPIC + N_DOC + N_DOC + N_TOPIC)  // 62,000 deg slots

// GEMM tile bookkeeping: 128-row tiles per etype
#define T_W  235   // ceil(30000/128)
#define T_T  8     // ceil(1000/128)
#define TILES_TOTAL (3 * T_W + 2 * T_T)            // 721
#define KCH  32
#define NCH  10    // ceil(300/32) -> padded K=320

// ---------------------------------------------------------------------------
// Static device scratch (no allocation allowed).  Wh in fp16 (halves agg
// gather traffic + GEMM store traffic; math stays fp32).
// ---------------------------------------------------------------------------
__device__ __half g_Wh_ww[(size_t)N_WORD  * D_OUT];
__device__ __half g_Wh_wt[(size_t)N_WORD  * D_OUT];
__device__ __half g_Wh_wd[(size_t)N_WORD  * D_OUT];
__device__ __half g_Wh_td[(size_t)N_TOPIC * D_OUT];
__device__ __half g_Wh_tt[(size_t)N_TOPIC * D_OUT];

__device__ __align__(16) int g_deg_ww[N_WORD];  __device__ int g_off_ww[N_WORD + 1];
__device__ __align__(16) int g_deg_wt[N_TOPIC]; __device__ int g_off_wt[N_TOPIC + 1];
__device__ __align__(16) int g_deg_wd[N_DOC];   __device__ int g_off_wd[N_DOC + 1];
__device__ __align__(16) int g_deg_td[N_DOC];   __device__ int g_off_td[N_DOC + 1];
__device__ __align__(16) int g_deg_tt[N_TOPIC]; __device__ int g_off_tt[N_TOPIC + 1];

// per-edge rank within its dst bucket (flat over all etypes)
__device__ __align__(16) int g_rank[E_TOT];

// dst-sorted packed (src, w) pairs
__device__ uint2 g_pair_ww[E_WW];
__device__ uint2 g_pair_wt[E_WT];
__device__ uint2 g_pair_wd[E_WD];
__device__ uint2 g_pair_td[E_TD];
__device__ uint2 g_pair_tt[E_TT];

__device__ __forceinline__ __half* Wh_ptr(int et) {
    switch (et) { case 0: return g_Wh_ww; case 1: return g_Wh_wt; case 2: return g_Wh_wd;
                  case 3: return g_Wh_td; default: return g_Wh_tt; }
}
__device__ __forceinline__ int* deg_ptr(int et) {
    switch (et) { case 0: return g_deg_ww; case 1: return g_deg_wt; case 2: return g_deg_wd;
                  case 3: return g_deg_td; default: return g_deg_tt; }
}
__device__ __forceinline__ int* off_ptr(int et) {
    switch (et) { case 0: return g_off_ww; case 1: return g_off_wt; case 2: return g_off_wd;
                  case 3: return g_off_td; default: return g_off_tt; }
}
__device__ __forceinline__ uint2* pair_ptr(int et) {
    switch (et) { case 0: return g_pair_ww; case 1: return g_pair_wt; case 2: return g_pair_wd;
                  case 3: return g_pair_td; default: return g_pair_tt; }
}
__device__ __forceinline__ int ndst_of(int et) {
    switch (et) { case 0: return N_WORD; case 1: return N_TOPIC; case 2: return N_DOC;
                  case 3: return N_DOC; default: return N_TOPIC; }
}

// fp16 row fragment load: 4 consecutive halves at column lane*4 -> float4
__device__ __forceinline__ float4 ldWh4(const __half* Wh, unsigned src, int lane) {
    uint2 raw = *(const uint2*)(Wh + (size_t)src * D_OUT + lane * 4);
    __half2 h0 = *reinterpret_cast<__half2*>(&raw.x);
    __half2 h1 = *reinterpret_cast<__half2*>(&raw.y);
    float2 f0 = __half22float2(h0);
    float2 f1 = __half22float2(h1);
    return make_float4(f0.x, f0.y, f1.x, f1.y);
}

// ---------------------------------------------------------------------------
// Pointer bundles
// ---------------------------------------------------------------------------
struct EdgeArgs {
    const int*   src[5];
    const int*   dst[5];
    const float* w[5];
};
struct GemmArgs {
    const float* featW;
    const float* featT;
    const float* Wm[5];
    const float* bias[5];
};

// flat-edge -> (etype, local index)
__device__ __forceinline__ void edge_map(int i, int& et, int& j) {
    if (i < E_WW)                        { et = 0; j = i; }
    else if (i < E_WW + E_WT)            { et = 1; j = i - E_WW; }
    else if (i < E_WW + E_WT + E_WD)     { et = 2; j = i - (E_WW + E_WT); }
    else if (i < E_TOT - E_TT)           { et = 3; j = i - (E_WW + E_WT + E_WD); }
    else                                 { et = 4; j = i - (E_TOT - E_TT); }
}

// ---------------------------------------------------------------------------
// Kernel 2: fused histogram, 4 edges/thread; atomic return = per-edge rank.
// deg[] zeroed by previous call's fill_all (module init on call 0).
// ---------------------------------------------------------------------------
__global__ void hist_all_kernel(EdgeArgs ea) {
    int i4 = (blockIdx.x * blockDim.x + threadIdx.x) * 4;
    if (i4 >= E_TOT) return;
    int et, j; edge_map(i4, et, j);
    int* deg = deg_ptr(et);
    int4 d4 = *(const int4*)(ea.dst[et] + j);
    int4 r4;
    r4.x = atomicAdd(&deg[d4.x], 1);
    r4.y = atomicAdd(&deg[d4.y], 1);
    r4.z = atomicAdd(&deg[d4.z], 1);
    r4.w = atomicAdd(&deg[d4.w], 1);
    *(int4*)(g_rank + i4) = r4;
}

// ---------------------------------------------------------------------------
// Kernel 3: fused scan, one block per etype (warp-shuffle, 2 barriers)
// ---------------------------------------------------------------------------
__global__ void scan_all_kernel() {
    const int et = blockIdx.x;
    const int n = ndst_of(et);
    int* deg = deg_ptr(et);
    int* off = off_ptr(et);
    __shared__ int warp_pre[32];
    __shared__ int s_total;

    const int t = threadIdx.x;
    const int lane = t & 31, wid = t >> 5;
    int chunk = (((n + 1023) >> 10) + 3) & ~3;
    int beg = t * chunk;
    int end = min(beg + chunk, n);

    int s = 0;
    int i = beg;
    for (; i + 4 <= end; i += 4) {
        int4 v = *(const int4*)(deg + i);
        s += v.x + v.y + v.z + v.w;
    }
    for (; i < end; i++) s += deg[i];

    int inc = s;
#pragma unroll
    for (int d = 1; d < 32; d <<= 1) {
        int v = __shfl_up_sync(0xFFFFFFFFu, inc, d);
        if (lane >= d) inc += v;
    }
    if (lane == 31) warp_pre[wid] = inc;
    __syncthreads();
    if (wid == 0) {
        int ws = warp_pre[lane];
        int winc = ws;
#pragma unroll
        for (int d = 1; d < 32; d <<= 1) {
            int v = __shfl_up_sync(0xFFFFFFFFu, winc, d);
            if (lane >= d) winc += v;
        }
        warp_pre[lane] = winc - ws;
        if (lane == 31) s_total = winc;
    }
    __syncthreads();

    int run = warp_pre[wid] + (inc - s);
    for (int j2 = beg; j2 < end; j2++) {
        off[j2] = run;
        run += deg[j2];
    }
    if (t == 0) off[n] = s_total;
}

// ---------------------------------------------------------------------------
// Kernel 4: atomic-free fill, 4 edges/thread; re-zeroes deg[] for next call
// ---------------------------------------------------------------------------
__global__ void fill_all_kernel(EdgeArgs ea) {
    int gid = blockIdx.x * blockDim.x + threadIdx.x;

    if (gid < N_NODES_TOT) {
        int k = gid;
        if      (k < N_WORD)                       g_deg_ww[k] = 0;
        else if (k < N_WORD + N_TOPIC)             g_deg_wt[k - N_WORD] = 0;
        else if (k < N_WORD + N_TOPIC + N_DOC)     g_deg_wd[k - (N_WORD + N_TOPIC)] = 0;
        else if (k < N_NODES_TOT - N_TOPIC)        g_deg_td[k - (N_WORD + N_TOPIC + N_DOC)] = 0;
        else                                       g_deg_tt[k - (N_NODES_TOT - N_TOPIC)] = 0;
    }

    int i4 = gid * 4;
    if (i4 >= E_TOT) return;
    int et, j; edge_map(i4, et, j);
    const int* off = off_ptr(et);
    uint2* pp = pair_ptr(et);
    int4   s4 = *(const int4*)(ea.src[et] + j);
    int4   d4 = *(const int4*)(ea.dst[et] + j);
    float4 w4 = *(const float4*)(ea.w[et] + j);
    int4   r4 = *(const int4*)(g_rank + i4);

    pp[off[d4.x] + r4.x] = make_uint2((unsigned)s4.x, __float_as_uint(w4.x));
    pp[off[d4.y] + r4.y] = make_uint2((unsigned)s4.y, __float_as_uint(w4.y));
    pp[off[d4.z] + r4.z] = make_uint2((unsigned)s4.z, __float_as_uint(w4.z));
    pp[off[d4.w] + r4.w] = make_uint2((unsigned)s4.w, __float_as_uint(w4.w));
}

// ---------------------------------------------------------------------------
// Kernel 5: fused tf32 GEMM with cp.async double buffering; fp16 epilogue.
// ---------------------------------------------------------------------------
__device__ __forceinline__ unsigned f2tf32(float x) {
    unsigned u; asm("cvt.rna.tf32.f32 %0, %1;" : "=r"(u) : "f"(x)); return u;
}
__device__ __forceinline__ void mma_tf32(float* c, const unsigned* a, const unsigned* b) {
    asm volatile(
        "mma.sync.aligned.m16n8k8.row.col.f32.tf32.tf32.f32 "
        "{%0,%1,%2,%3}, {%4,%5,%6,%7}, {%8,%9}, {%0,%1,%2,%3};\n"
        : "+f"(c[0]), "+f"(c[1]), "+f"(c[2]), "+f"(c[3])
        : "r"(a[0]), "r"(a[1]), "r"(a[2]), "r"(a[3]), "r"(b[0]), "r"(b[1]));
}
__device__ __forceinline__ void cp_async16(void* smem, const void* gmem, int valid_bytes) {
    unsigned sa = (unsigned)__cvta_generic_to_shared(smem);
    asm volatile("cp.async.cg.shared.global [%0], [%1], 16, %2;\n"
                 :: "r"(sa), "l"(gmem), "r"(valid_bytes));
}

__global__ void __launch_bounds__(256, 2)
gemm_tf32_kernel(GemmArgs ga) {
    __shared__ float Af[2][128][36];    // [buf][row][k]
    __shared__ float Bf[2][32][136];    // [buf][k][n]

    int bt = blockIdx.x;
    int et, tile;
    if      (bt < T_W)                 { et = 0; tile = bt; }
    else if (bt < 2 * T_W)             { et = 1; tile = bt - T_W; }
    else if (bt < 3 * T_W)             { et = 2; tile = bt - 2 * T_W; }
    else if (bt < 3 * T_W + T_T)       { et = 3; tile = bt - 3 * T_W; }
    else                               { et = 4; tile = bt - (3 * T_W + T_T); }

    const float* A    = (et < 3) ? ga.featW : ga.featT;
    const int    M    = (et < 3) ? N_WORD : N_TOPIC;
    const float* Wm   = ga.Wm[et];
    const float* bias = ga.bias[et];
    __half*      C    = Wh_ptr(et);

    const int row0 = tile * 128;
    const int tid  = threadIdx.x;
    const int lane = tid & 31, wid = tid >> 5;
    const int wm = wid & 3, wn = wid >> 2;       // warp grid 4 x 2
    const int g  = lane >> 2, tg = lane & 3;     // groupID / thread-in-group

    float acc[2][8][4];
#pragma unroll
    for (int mi = 0; mi < 2; mi++)
#pragma unroll
        for (int ni = 0; ni < 8; ni++)
#pragma unroll
            for (int q = 0; q < 4; q++) acc[mi][ni][q] = 0.0f;

    auto load_chunk = [&](int k0, int buf) {
#pragma unroll
        for (int it = 0; it < 4; it++) {
            int slot = it * 256 + tid;           // 0..1023
            int r = slot >> 3, kq = slot & 7;
            int gr = row0 + r, gk = k0 + kq * 4;
            int ok = (gr < M && gk + 4 <= D_IN);
            const float* gp = A + (size_t)(ok ? gr : 0) * D_IN + (ok ? gk : 0);
            cp_async16(&Af[buf][r][kq * 4], gp, ok ? 16 : 0);
        }
#pragma unroll
        for (int it = 0; it < 4; it++) {
            int slot = it * 256 + tid;           // 0..1023
            int kk = slot >> 5, cq = slot & 31;
            int gk = k0 + kk;
            int ok = (gk < D_IN);
            const float* gp = Wm + (size_t)(ok ? gk : 0) * D_OUT + cq * 4;
            cp_async16(&Bf[buf][kk][cq * 4], gp, ok ? 16 : 0);
        }
        asm volatile("cp.async.commit_group;\n");
    };

    load_chunk(0, 0);
    for (int c = 0; c < NCH; c++) {
        int buf = c & 1;
        if (c + 1 < NCH) {
            load_chunk((c + 1) * KCH, buf ^ 1);
            asm volatile("cp.async.wait_group 1;\n");
        } else {
            asm volatile("cp.async.wait_group 0;\n");
        }
        __syncthreads();

#pragma unroll
        for (int ks = 0; ks < KCH; ks += 8) {
            unsigned a[2][4], b[8][2];
#pragma unroll
            for (int mi = 0; mi < 2; mi++) {
                int r0 = wm * 32 + mi * 16 + g;
                a[mi][0] = f2tf32(Af[buf][r0][ks + tg]);
                a[mi][1] = f2tf32(Af[buf][r0 + 8][ks + tg]);
                a[mi][2] = f2tf32(Af[buf][r0][ks + tg + 4]);
                a[mi][3] = f2tf32(Af[buf][r0 + 8][ks + tg + 4]);
            }
#pragma unroll
            for (int ni = 0; ni < 8; ni++) {
                int n = wn * 64 + ni * 8 + g;
                b[ni][0] = f2tf32(Bf[buf][ks + tg][n]);
                b[ni][1] = f2tf32(Bf[buf][ks + tg + 4][n]);
            }
#pragma unroll
            for (int mi = 0; mi < 2; mi++)
#pragma unroll
                for (int ni = 0; ni < 8; ni++)
                    mma_tf32(acc[mi][ni], a[mi], b[ni]);
        }
        __syncthreads();
    }

    // ---- epilogue: + bias, convert to fp16, store half2
#pragma unroll
    for (int mi = 0; mi < 2; mi++) {
        int r = row0 + wm * 32 + mi * 16 + g;
#pragma unroll
        for (int ni = 0; ni < 8; ni++) {
            int cb = wn * 64 + ni * 8 + tg * 2;
            float b0 = bias[cb], b1 = bias[cb + 1];
            if (r < M) {
                __half2 o = __floats2half2_rn(acc[mi][ni][0] + b0, acc[mi][ni][1] + b1);
                *(__half2*)(C + (size_t)r * D_OUT + cb) = o;
            }
            if (r + 8 < M) {
                __half2 o = __floats2half2_rn(acc[mi][ni][2] + b0, acc[mi][ni][3] + b1);
                *(__half2*)(C + (size_t)(r + 8) * D_OUT + cb) = o;
            }
        }
    }
}

// ---------------------------------------------------------------------------
// Kernel 6a: warp-per-node aggregation for word + doc nodes.
// Pair loads via __ldcs (read-once; keep L2 for Wh rows).
// ---------------------------------------------------------------------------
__device__ __forceinline__ void seg_mean_acc(int et, int d, int lane, float4& res) {
    const int*   off = off_ptr(et);
    const uint2* pp  = pair_ptr(et);
    const __half* Wh = Wh_ptr(et);
    int beg = off[d], end = off[d + 1];
    float4 acc0 = make_float4(0.f, 0.f, 0.f, 0.f);
    float4 acc1 = make_float4(0.f, 0.f, 0.f, 0.f);
    int j = beg;
    for (; j + 4 <= end; j += 4) {
        uint2 p0 = __ldcs(pp + j),     p1 = __ldcs(pp + j + 1);
        uint2 p2 = __ldcs(pp + j + 2), p3 = __ldcs(pp + j + 3);
        float w0 = __uint_as_float(p0.y), w1 = __uint_as_float(p1.y);
        float w2 = __uint_as_float(p2.y), w3 = __uint_as_float(p3.y);
        float4 v0 = ldWh4(Wh, p0.x, lane);
        float4 v1 = ldWh4(Wh, p1.x, lane);
        float4 v2 = ldWh4(Wh, p2.x, lane);
        float4 v3 = ldWh4(Wh, p3.x, lane);
        acc0.x = fmaf(w0, v0.x, acc0.x); acc0.y = fmaf(w0, v0.y, acc0.y);
        acc0.z = fmaf(w0, v0.z, acc0.z); acc0.w = fmaf(w0, v0.w, acc0.w);
        acc1.x = fmaf(w1, v1.x, acc1.x); acc1.y = fmaf(w1, v1.y, acc1.y);
        acc1.z = fmaf(w1, v1.z, acc1.z); acc1.w = fmaf(w1, v1.w, acc1.w);
        acc0.x = fmaf(w2, v2.x, acc0.x); acc0.y = fmaf(w2, v2.y, acc0.y);
        acc0.z = fmaf(w2, v2.z, acc0.z); acc0.w = fmaf(w2, v2.w, acc0.w);
        acc1.x = fmaf(w3, v3.x, acc1.x); acc1.y = fmaf(w3, v3.y, acc1.y);
        acc1.z = fmaf(w3, v3.z, acc1.z); acc1.w = fmaf(w3, v3.w, acc1.w);
    }
    for (; j < end; j++) {
        uint2 p = __ldcs(pp + j);
        float w = __uint_as_float(p.y);
        float4 v = ldWh4(Wh, p.x, lane);
        acc0.x = fmaf(w, v.x, acc0.x); acc0.y = fmaf(w, v.y, acc0.y);
        acc0.z = fmaf(w, v.z, acc0.z); acc0.w = fmaf(w, v.w, acc0.w);
    }
    float inv = 1.0f / fmaxf((float)(end - beg), 1.0f);
    res.x += (acc0.x + acc1.x) * inv;
    res.y += (acc0.y + acc1.y) * inv;
    res.z += (acc0.z + acc1.z) * inv;
    res.w += (acc0.w + acc1.w) * inv;
}

__global__ void agg_wd_kernel(float* __restrict__ out) {
    int gw   = (blockIdx.x * blockDim.x + threadIdx.x) >> 5;
    int lane = threadIdx.x & 31;
    if (gw >= N_WD) return;
    float4 res = make_float4(0.f, 0.f, 0.f, 0.f);
    size_t orow;
    if (gw < N_WORD) {
        seg_mean_acc(0, gw, lane, res);
        orow = gw;
    } else {
        int d = gw - N_WORD;
        seg_mean_acc(2, d, lane, res);
        seg_mean_acc(3, d, lane, res);
        orow = (size_t)(N_WORD + N_TOPIC) + d;
    }
    *(float4*)(out + orow * D_OUT + lane * 4) = res;
}

// ---------------------------------------------------------------------------
// Kernel 6b: block-per-node aggregation for topic nodes (long segments)
// ---------------------------------------------------------------------------
__global__ void __launch_bounds__(256) agg_topic_kernel(float* __restrict__ out) {
    __shared__ float4 sm[8][32];
    const int d    = blockIdx.x;
    const int lane = threadIdx.x & 31;
    const int wid  = threadIdx.x >> 5;
    float4 res = make_float4(0.f, 0.f, 0.f, 0.f);

#pragma unroll
    for (int pass = 0; pass < 2; pass++) {
        const int    et  = pass ? 4 : 1;
        const int*   off = off_ptr(et);
        const uint2* pp  = pair_ptr(et);
        const __half* Wh = Wh_ptr(et);
        int beg = off[d], end = off[d + 1];
        float4 acc = make_float4(0.f, 0.f, 0.f, 0.f);
        int j = beg + wid;
        for (; j + 8 < end; j += 16) {
            uint2 pA = __ldcs(pp + j), pB = __ldcs(pp + j + 8);
            float wA = __uint_as_float(pA.y), wB = __uint_as_float(pB.y);
            float4 vA = ldWh4(Wh, pA.x, lane);
            float4 vB = ldWh4(Wh, pB.x, lane);
            acc.x = fmaf(wA, vA.x, acc.x); acc.y = fmaf(wA, vA.y, acc.y);
            acc.z = fmaf(wA, vA.z, acc.z); acc.w = fmaf(wA, vA.w, acc.w);
            acc.x = fmaf(wB, vB.x, acc.x); acc.y = fmaf(wB, vB.y, acc.y);
            acc.z = fmaf(wB, vB.z, acc.z); acc.w = fmaf(wB, vB.w, acc.w);
        }
        if (j < end) {
            uint2 p = __ldcs(pp + j);
            float w = __uint_as_float(p.y);
            float4 v = ldWh4(Wh, p.x, lane);
            acc.x = fmaf(w, v.x, acc.x); acc.y = fmaf(w, v.y, acc.y);
            acc.z = fmaf(w, v.z, acc.z); acc.w = fmaf(w, v.w, acc.w);
        }
        sm[wid][lane] = acc;
        __syncthreads();
        if (wid == 0) {
            float4 s = sm[0][lane];
#pragma unroll
            for (int w2 = 1; w2 < 8; w2++) {
                float4 t = sm[w2][lane];
                s.x += t.x; s.y += t.y; s.z += t.z; s.w += t.w;
            }
            float inv = 1.0f / fmaxf((float)(end - beg), 1.0f);
            res.x += s.x * inv; res.y += s.y * inv;
            res.z += s.z * inv; res.w += s.w * inv;
        }
        __syncthreads();
    }
    if (wid == 0)
        *(float4*)(out + (size_t)(N_WORD + d) * D_OUT + lane * 4) = res;
}

// ---------------------------------------------------------------------------
// Launch: GEMM + topic-agg on side stream, CSR build + word/doc agg on main.
// ---------------------------------------------------------------------------
extern "C" void kernel_launch(void* const* d_in, const int* in_sizes, int n_in,
                              void* d_out, int out_size) {
    (void)out_size;

    static cudaStream_t s_side = nullptr;
    static cudaEvent_t  ev_fork = nullptr, ev_join = nullptr,
                        ev_fill = nullptr, ev_side = nullptr;
    if (!s_side) {
        cudaStreamCreateWithFlags(&s_side, cudaStreamNonBlocking);
        cudaEventCreateWithFlags(&ev_fork, cudaEventDisableTiming);
        cudaEventCreateWithFlags(&ev_join, cudaEventDisableTiming);
        cudaEventCreateWithFlags(&ev_fill, cudaEventDisableTiming);
        cudaEventCreateWithFlags(&ev_side, cudaEventDisableTiming);
    }

    // Resolve input ordering (W matrices are 38400 elems)
    int iS[5], iD[5], iW_[5], iWm[5], iB[5];
    bool interleaved = (n_in >= 7 && in_sizes[5] == D_IN * D_OUT);
    for (int et = 0; et < 5; et++) {
        if (interleaved) {
            int base = 2 + et * 5;
            iS[et] = base; iD[et] = base + 1; iW_[et] = base + 2;
            iWm[et] = base + 3; iB[et] = base + 4;
        } else {
            iS[et] = 2 + et * 3; iD[et] = 3 + et * 3; iW_[et] = 4 + et * 3;
            iWm[et] = 17 + et * 2; iB[et] = 18 + et * 2;
        }
    }

    EdgeArgs ea;
    GemmArgs ga;
    ga.featW = (const float*)d_in[0];
    ga.featT = (const float*)d_in[1];
    for (int et = 0; et < 5; et++) {
        ea.src[et]  = (const int*)d_in[iS[et]];
        ea.dst[et]  = (const int*)d_in[iD[et]];
        ea.w[et]    = (const float*)d_in[iW_[et]];
        ga.Wm[et]   = (const float*)d_in[iWm[et]];
        ga.bias[et] = (const float*)d_in[iB[et]];
    }
    float* out = (float*)d_out;

    // Fork: GEMM on side stream (independent of CSR build)
    cudaEventRecord(ev_fork, 0);
    cudaStreamWaitEvent(s_side, ev_fork, 0);
    gemm_tf32_kernel<<<TILES_TOTAL, 256, 0, s_side>>>(ga);
    cudaEventRecord(ev_join, s_side);

    // Main stream: CSR build (deg zeroed by previous call's fill / module init)
    hist_all_kernel<<<(E_TOT / 4 + 255) / 256, 256>>>(ea);
    scan_all_kernel<<<5, 1024>>>();
    fill_all_kernel<<<(E_TOT / 4 + 255) / 256, 256>>>(ea);
    cudaEventRecord(ev_fill, 0);

    // Side stream: topic aggregation (after gemm in-order; wait for fill)
    cudaStreamWaitEvent(s_side, ev_fill, 0);
    agg_topic_kernel<<<N_TOPIC, 256, 0, s_side>>>(out);
    cudaEventRecord(ev_side, s_side);

    // Main stream: word+doc aggregation (needs gemm join), then join side
    cudaStreamWaitEvent(0, ev_join, 0);
    agg_wd_kernel<<<(N_WD * 32 + 255) / 256, 256>>>(out);
    cudaStreamWaitEvent(0, ev_side, 0);
}